// round 9
// baseline (speedup 1.0000x reference)
#include <cuda_runtime.h>
#include <cuda_fp16.h>
#include <cstdint>

#define N_MAX 100000
#define E_MAX 1600000
#define NBLK_SCAN 128   // max scan blocks (n/1024 <= 98)
#define AGG_NPB 64      // nodes per fused block
#define SS_STRIDE 68    // padded row stride for sS (floats); 68*4B = 17*16B (float4-aligned rows)

// ---------------- scratch (static device memory; no allocation) ----------------
__device__ int   g_deg_out[N_MAX];
__device__ int   g_deg_in[N_MAX];
__device__ float g_norm_src[N_MAX];
__device__ float g_norm_dst[N_MAX];
__device__ int   g_row_ptr[N_MAX + 1];
__device__ int   g_fill[N_MAX];
__device__ int   g_col[E_MAX];
__device__ __half g_a[N_MAX * 64];  // ping: pre-scaled features (fp16)
__device__ __half g_b[N_MAX * 64];  // pong
__device__ int g_blk_sum[NBLK_SCAN];
__device__ volatile int g_blk_flag[NBLK_SCAN];

// ---------------- threefry-2x32 (exact JAX algorithm, partitionable path) ----------------
__device__ __forceinline__ void d_threefry(uint32_t k0, uint32_t k1,
                                           uint32_t x0, uint32_t x1,
                                           uint32_t& y0, uint32_t& y1) {
    uint32_t k2 = k0 ^ k1 ^ 0x1BD11BDAu;
    x0 += k0; x1 += k1;
#define TFR(r) { x0 += x1; x1 = __funnelshift_l(x1, x1, r); x1 ^= x0; }
    TFR(13) TFR(15) TFR(26) TFR(6)
    x0 += k1; x1 += k2 + 1u;
    TFR(17) TFR(29) TFR(16) TFR(24)
    x0 += k2; x1 += k0 + 2u;
    TFR(13) TFR(15) TFR(26) TFR(6)
    x0 += k0; x1 += k1 + 3u;
    TFR(17) TFR(29) TFR(16) TFR(24)
    x0 += k1; x1 += k2 + 4u;
    TFR(13) TFR(15) TFR(26) TFR(6)
    x0 += k2; x1 += k0 + 5u;
#undef TFR
    y0 = x0; y1 = x1;
}

static inline uint32_t h_rotl(uint32_t x, int r) { return (x << r) | (x >> (32 - r)); }
static void h_threefry(uint32_t k0, uint32_t k1, uint32_t x0, uint32_t x1,
                       uint32_t& y0, uint32_t& y1) {
    uint32_t k2 = k0 ^ k1 ^ 0x1BD11BDAu;
    x0 += k0; x1 += k1;
#define TFR(r) { x0 += x1; x1 = h_rotl(x1, r); x1 ^= x0; }
    TFR(13) TFR(15) TFR(26) TFR(6)
    x0 += k1; x1 += k2 + 1u;
    TFR(17) TFR(29) TFR(16) TFR(24)
    x0 += k2; x1 += k0 + 2u;
    TFR(13) TFR(15) TFR(26) TFR(6)
    x0 += k0; x1 += k1 + 3u;
    TFR(17) TFR(29) TFR(16) TFR(24)
    x0 += k1; x1 += k2 + 4u;
    TFR(13) TFR(15) TFR(26) TFR(6)
    x0 += k2; x1 += k0 + 5u;
#undef TFR
    y0 = x0; y1 = x1;
}

// ---------------- graph prep ----------------
__global__ void k_zero(int n) {
    int i = blockIdx.x * blockDim.x + threadIdx.x;
    if (i < n) { g_deg_out[i] = 0; g_deg_in[i] = 0; }
    if (i < NBLK_SCAN) { g_blk_flag[i] = 0; g_blk_sum[i] = 0; }
}

__global__ void k_degree(const int* __restrict__ src, const int* __restrict__ dst, int e) {
    int i = blockIdx.x * blockDim.x + threadIdx.x;
    if (i < e) {
        atomicAdd(&g_deg_out[src[i]], 1);
        atomicAdd(&g_deg_in[dst[i]], 1);
    }
}

// fused: norms + single-pass exclusive scan (decoupled lookback) -> row_ptr / fill
// + U0 = fp16(norm_src * x)
__global__ void k_scan_norm_scale(const float* __restrict__ x, int n, int e) {
    __shared__ int s[1024];
    __shared__ float snorm[1024];
    __shared__ int s_prefix;
    int b = blockIdx.x, t = threadIdx.x, i = b * 1024 + t;
    int din = (i < n) ? g_deg_in[i] : 0;
    float ns = 0.f;
    if (i < n) {
        int a = g_deg_out[i];
        ns = (a > 0) ? rsqrtf((float)a) : 0.f;
        g_norm_src[i] = ns;
        g_norm_dst[i] = (din > 0) ? rsqrtf((float)din) : 0.f;
    }
    snorm[t] = ns;
    s[t] = din;
    __syncthreads();
    for (int off = 1; off < 1024; off <<= 1) {
        int a = (t >= off) ? s[t - off] : 0;
        __syncthreads();
        s[t] += a;
        __syncthreads();
    }
    if (t == 0) {
        s_prefix = 0;
        g_blk_sum[b] = s[1023];
        __threadfence();
        g_blk_flag[b] = 1;
    }
    __syncthreads();
    if (t < b) {
        while (g_blk_flag[t] == 0) {}
        int v = *((volatile int*)&g_blk_sum[t]);
        atomicAdd(&s_prefix, v);
    }
    __syncthreads();
    int excl = s[t] - din + s_prefix;
    if (i < n) { g_row_ptr[i] = excl; g_fill[i] = excl; }
    if (i == 0) g_row_ptr[n] = e;

    // fused scale: g_a[node][:] = fp16(norm_src[node] * x[node][:])
    const float4* x4 = (const float4*)x;
    int f4base = b * 1024 * 16;   // first float4 index of this block's nodes
#pragma unroll
    for (int q = 0; q < 16; q++) {
        int idx = f4base + q * 1024 + t;
        if (idx < n * 16) {
            float nv = snorm[(idx >> 4) - b * 1024];
            float4 v = x4[idx];
            __half2 h0 = __floats2half2_rn(v.x * nv, v.y * nv);
            __half2 h1 = __floats2half2_rn(v.z * nv, v.w * nv);
            uint2 pk;
            pk.x = *reinterpret_cast<uint32_t*>(&h0);
            pk.y = *reinterpret_cast<uint32_t*>(&h1);
            ((uint2*)g_a)[idx] = pk;
        }
    }
}

__global__ void k_csr(const int* __restrict__ src, const int* __restrict__ dst, int e) {
    int i = blockIdx.x * blockDim.x + threadIdx.x;
    if (i < e) {
        int p = atomicAdd(&g_fill[dst[i]], 1);
        g_col[p] = src[i];
    }
}

// ---------------- packed f32x2 helpers ----------------
__device__ __forceinline__ unsigned long long pk2(float x, float y) {
    unsigned long long r;
    asm("mov.b64 %0, {%1,%2};" : "=l"(r) : "f"(x), "f"(y));
    return r;
}
__device__ __forceinline__ void fma2(unsigned long long& d, unsigned long long a, unsigned long long b) {
    asm("fma.rn.f32x2 %0, %1, %2, %0;" : "+l"(d) : "l"(a), "l"(b));
}
__device__ __forceinline__ float2 upk2(unsigned long long v) {
    float2 r;
    asm("mov.b64 {%0,%1}, %2;" : "=f"(r.x), "=f"(r.y) : "l"(v));
    return r;
}

// load 4 consecutive fp16 features (8B) and accumulate into float4
__device__ __forceinline__ void acc_h4(float4& acc, const __half* p) {
    float2 raw = *(const float2*)p;   // 8B carrier
    __half2 h0 = *reinterpret_cast<__half2*>(&raw.x);
    __half2 h1 = *reinterpret_cast<__half2*>(&raw.y);
    float2 f0 = __half22float2(h0);
    float2 f1 = __half22float2(h1);
    acc.x += f0.x; acc.y += f0.y; acc.z += f1.x; acc.w += f1.y;
}

// ---------------- fused aggregation + tiled GEMM + epilogue ----------------
// Block = 256 threads, 64 nodes.
//  phase 1: warp w gathers nodes base+8w..base+8w+7. Split-warp gather:
//           lanes 0-15 take even edge, 16-31 odd edge; each lane loads 4 fp16
//           cols (LDG.64). 1 LDG instr/edge, 128B/edge. shfl-combine halves.
//           Dropout threefry interleaved per node (overlaps in-flight gathers).
//  phase 2: tiled GEMM on smem S (4 rows x 2 cpairs per thread) vs staged W
//  phase 3: epilogue (norm_dst, bias, relu, dropout, norm_src prescale, fp16 out)
template <int LAYER>
__global__ void __launch_bounds__(256) k_aggemm(const __half* __restrict__ U,
                                                void* __restrict__ Unext,
                                                const float* __restrict__ W,
                                                const float* __restrict__ bias,
                                                uint32_t key0, uint32_t key1, int n) {
    __shared__ unsigned long long sW[64 * 32]; // [k][cpair] packed (W[k][2c], W[k][2c+1])
    __shared__ float sS[AGG_NPB * SS_STRIDE];  // [local node][k], padded
    int t = threadIdx.x;
    int base = blockIdx.x * AGG_NPB;
    int w = t >> 5, lane = t & 31;
    int h = lane >> 4, laneL = lane & 15;
    int rid = t >> 4;       // epilogue row id
    int cid = t & 15;       // epilogue col-pair id

    // stage W (16KB; one-time per 64 nodes)
    const float2* Wv = (const float2*)W;
#pragma unroll
    for (int q = 0; q < 8; q++) {
        int idx = t + q * 256;
        float2 wv = Wv[idx];
        sW[idx] = pk2(wv.x, wv.y);
    }

    // phase 1: gather-sum 8 nodes per warp; dropout masks interleaved
    uint32_t keepmask = 0;
#pragma unroll 1
    for (int r = 0; r < 8; r++) {
        int node = base + w * 8 + r;
        int s = 0, e = 0;
        if (node < n) { s = g_row_ptr[node]; e = g_row_ptr[node + 1]; }

        if (LAYER != 2) {
            int en = base + rid + 16 * (r >> 1);
            int ec = cid + 16 * (r & 1);
            uint32_t idx = (uint32_t)en * 64u + 2u * (uint32_t)ec;
            uint32_t y0, y1, z0, z1;
            d_threefry(key0, key1, 0u, idx, y0, y1);
            d_threefry(key0, key1, 0u, idx + 1u, z0, z1);
            keepmask |= (1u ^ ((y0 ^ y1) >> 31)) << (2 * r);
            keepmask |= (1u ^ ((z0 ^ z1) >> 31)) << (2 * r + 1);
        }

        float4 acc = make_float4(0.f, 0.f, 0.f, 0.f);
        int i = s;
        for (; i + 4 <= e; i += 4) {
            int ua = g_col[i + h];          // lanes 0-15: edge i ; 16-31: edge i+1
            int ub = g_col[i + 2 + h];      // edges i+2 / i+3
            acc_h4(acc, U + ua * 64 + laneL * 4);
            acc_h4(acc, U + ub * 64 + laneL * 4);
        }
        if (i + 2 <= e) {
            int ua = g_col[i + h];
            acc_h4(acc, U + ua * 64 + laneL * 4);
            i += 2;
        }
        if (i < e && h == 0) {
            int u = g_col[i];
            acc_h4(acc, U + u * 64 + laneL * 4);
        }
        // combine odd-edge half into even-edge half
        acc.x += __shfl_down_sync(0xFFFFFFFFu, acc.x, 16);
        acc.y += __shfl_down_sync(0xFFFFFFFFu, acc.y, 16);
        acc.z += __shfl_down_sync(0xFFFFFFFFu, acc.z, 16);
        acc.w += __shfl_down_sync(0xFFFFFFFFu, acc.w, 16);
        if (h == 0)
            *(float4*)&sS[(w * 8 + r) * SS_STRIDE + laneL * 4] = acc;
    }
    __syncthreads();

    // phase 2: tiled GEMM. thread: rows rid+16i (i=0..3), cpairs cid+16j (j=0..1).
    unsigned long long acc2[4][2];
#pragma unroll
    for (int i = 0; i < 4; i++)
#pragma unroll
        for (int j = 0; j < 2; j++) acc2[i][j] = 0ull;

#pragma unroll 8
    for (int k = 0; k < 64; k++) {
        unsigned long long a[4], b[2];
#pragma unroll
        for (int i = 0; i < 4; i++) {
            float hh = sS[(rid + 16 * i) * SS_STRIDE + k];
            a[i] = pk2(hh, hh);
        }
#pragma unroll
        for (int j = 0; j < 2; j++) b[j] = sW[k * 32 + cid + 16 * j];
#pragma unroll
        for (int i = 0; i < 4; i++)
#pragma unroll
            for (int j = 0; j < 2; j++) fma2(acc2[i][j], a[i], b[j]);
    }

    // phase 3: epilogue (element pair r = 2*i + j  ->  keepmask bits 2r, 2r+1)
#pragma unroll
    for (int i = 0; i < 4; i++) {
        int node = base + rid + 16 * i;
        if (node < n) {
            float nd = g_norm_dst[node];
            float ns = (LAYER != 2) ? g_norm_src[node] : 0.f;
#pragma unroll
            for (int j = 0; j < 2; j++) {
                int c = cid + 16 * j;
                float2 bb = ((const float2*)bias)[c];
                float2 v = upk2(acc2[i][j]);
                float ox = v.x * nd + bb.x;
                float oy = v.y * nd + bb.y;
                if (LAYER != 2) {
                    ox = fmaxf(ox, 0.f);
                    oy = fmaxf(oy, 0.f);
                    int r = 2 * i + j;
                    bool keep0 = (keepmask >> (2 * r)) & 1u;
                    bool keep1 = (keepmask >> (2 * r + 1)) & 1u;
                    ox = keep0 ? ox * 2.f * ns : 0.f;
                    oy = keep1 ? oy * 2.f * ns : 0.f;
                    ((__half2*)Unext)[node * 32 + c] = __floats2half2_rn(ox, oy);
                } else {
                    ((float2*)Unext)[node * 32 + c] = make_float2(ox, oy);
                }
            }
        }
    }
}

// ---------------- launch ----------------
extern "C" void kernel_launch(void* const* d_in, const int* in_sizes, int n_in,
                              void* d_out, int out_size) {
    const float* x  = (const float*)d_in[0];
    const float* W0 = (const float*)d_in[1];
    const float* b0 = (const float*)d_in[2];
    const float* W1 = (const float*)d_in[3];
    const float* b1 = (const float*)d_in[4];
    const float* W2 = (const float*)d_in[5];
    const float* b2 = (const float*)d_in[6];
    const int*   src = (const int*)d_in[7];
    const int*   dst = (const int*)d_in[8];
    int n = in_sizes[0] / 64;
    int e = in_sizes[7];
    float* out = (float*)d_out;

    int nb = (n + 1023) / 1024;  // <= 98: all scan blocks resident, lookback safe

    uint32_t d0k0, d0k1, d1k0, d1k1;
    h_threefry(0u, 1u, 0u, 0u, d0k0, d0k1);
    h_threefry(0u, 1u, 0u, 1u, d1k0, d1k1);

    __half* gA; cudaGetSymbolAddress((void**)&gA, g_a);
    __half* gB; cudaGetSymbolAddress((void**)&gB, g_b);

    int aB = (n + AGG_NPB - 1) / AGG_NPB;

    k_zero<<<(n + 255) / 256, 256>>>(n);
    k_degree<<<(e + 255) / 256, 256>>>(src, dst, e);
    k_scan_norm_scale<<<nb, 1024>>>(x, n, e);
    k_csr<<<(e + 255) / 256, 256>>>(src, dst, e);

    k_aggemm<0><<<aB, 256>>>(gA, gB, W0, b0, d0k0, d0k1, n);
    k_aggemm<1><<<aB, 256>>>(gB, gA, W1, b1, d1k0, d1k1, n);
    k_aggemm<2><<<aB, 256>>>(gA, out, W2, b2, 0u, 0u, n);
}

// round 10
// speedup vs baseline: 1.3780x; 1.3780x over previous
#include <cuda_runtime.h>
#include <cstdint>

#define N_MAX 100000
#define E_MAX 1600000
#define NBLK_SCAN 128   // max scan blocks (n/1024 <= 98)
#define AGG_NPB 64      // nodes per fused block
#define SS_STRIDE 66    // padded row stride for sS (floats)

// ---------------- scratch (static device memory; no allocation) ----------------
__device__ int   g_deg_out[N_MAX];
__device__ int   g_deg_in[N_MAX];
__device__ float g_norm_src[N_MAX];
__device__ float g_norm_dst[N_MAX];
__device__ int   g_row_ptr[N_MAX + 1];
__device__ int   g_fill[N_MAX];
__device__ int   g_col[E_MAX];
__device__ float g_a[N_MAX * 64];   // ping: pre-scaled features (norm_src * h)
__device__ float g_b[N_MAX * 64];   // pong
__device__ int g_blk_sum[NBLK_SCAN];
__device__ int g_blk_flag[NBLK_SCAN];

// ---------------- threefry-2x32 (exact JAX algorithm, partitionable path) ----------------
__device__ __forceinline__ void d_threefry(uint32_t k0, uint32_t k1,
                                           uint32_t x0, uint32_t x1,
                                           uint32_t& y0, uint32_t& y1) {
    uint32_t k2 = k0 ^ k1 ^ 0x1BD11BDAu;
    x0 += k0; x1 += k1;
#define TFR(r) { x0 += x1; x1 = __funnelshift_l(x1, x1, r); x1 ^= x0; }
    TFR(13) TFR(15) TFR(26) TFR(6)
    x0 += k1; x1 += k2 + 1u;
    TFR(17) TFR(29) TFR(16) TFR(24)
    x0 += k2; x1 += k0 + 2u;
    TFR(13) TFR(15) TFR(26) TFR(6)
    x0 += k0; x1 += k1 + 3u;
    TFR(17) TFR(29) TFR(16) TFR(24)
    x0 += k1; x1 += k2 + 4u;
    TFR(13) TFR(15) TFR(26) TFR(6)
    x0 += k2; x1 += k0 + 5u;
#undef TFR
    y0 = x0; y1 = x1;
}

static inline uint32_t h_rotl(uint32_t x, int r) { return (x << r) | (x >> (32 - r)); }
static void h_threefry(uint32_t k0, uint32_t k1, uint32_t x0, uint32_t x1,
                       uint32_t& y0, uint32_t& y1) {
    uint32_t k2 = k0 ^ k1 ^ 0x1BD11BDAu;
    x0 += k0; x1 += k1;
#define TFR(r) { x0 += x1; x1 = h_rotl(x1, r); x1 ^= x0; }
    TFR(13) TFR(15) TFR(26) TFR(6)
    x0 += k1; x1 += k2 + 1u;
    TFR(17) TFR(29) TFR(16) TFR(24)
    x0 += k2; x1 += k0 + 2u;
    TFR(13) TFR(15) TFR(26) TFR(6)
    x0 += k0; x1 += k1 + 3u;
    TFR(17) TFR(29) TFR(16) TFR(24)
    x0 += k1; x1 += k2 + 4u;
    TFR(13) TFR(15) TFR(26) TFR(6)
    x0 += k2; x1 += k0 + 5u;
#undef TFR
    y0 = x0; y1 = x1;
}

// ---------------- graph prep ----------------
__global__ void k_degree(const int* __restrict__ src, const int* __restrict__ dst, int e) {
    int i = blockIdx.x * blockDim.x + threadIdx.x;
    if (i < e) {
        atomicAdd(&g_deg_out[src[i]], 1);
        atomicAdd(&g_deg_in[dst[i]], 1);
    }
}

// fused: norms + single-pass exclusive scan (decoupled lookback) -> row_ptr / fill
// + U0 = norm_src * x  (smem-shared norms, coalesced float4)
__global__ void k_scan_norm_scale(const float* __restrict__ x, int n, int e) {
    __shared__ int s[1024];
    __shared__ float snorm[1024];
    __shared__ int s_prefix;
    int b = blockIdx.x, t = threadIdx.x, i = b * 1024 + t;
    int din = (i < n) ? g_deg_in[i] : 0;
    float ns = 0.f;
    if (i < n) {
        int a = g_deg_out[i];
        ns = (a > 0) ? rsqrtf((float)a) : 0.f;
        g_norm_src[i] = ns;
        g_norm_dst[i] = (din > 0) ? rsqrtf((float)din) : 0.f;
    }
    snorm[t] = ns;
    s[t] = din;
    __syncthreads();
    for (int off = 1; off < 1024; off <<= 1) {
        int a = (t >= off) ? s[t - off] : 0;
        __syncthreads();
        s[t] += a;
        __syncthreads();
    }
    if (t == 0) {
        s_prefix = 0;
        g_blk_sum[b] = s[1023];
        __threadfence();
        *((volatile int*)&g_blk_flag[b]) = 1;
    }
    __syncthreads();
    if (t < b) {
        while (*((volatile int*)&g_blk_flag[t]) == 0) {}
        int v = *((volatile int*)&g_blk_sum[t]);
        atomicAdd(&s_prefix, v);
    }
    __syncthreads();
    int excl = s[t] - din + s_prefix;
    if (i < n) { g_row_ptr[i] = excl; g_fill[i] = excl; }
    if (i == 0) g_row_ptr[n] = e;

    // fused scale: g_a[node][:] = norm_src[node] * x[node][:]
    const float4* x4 = (const float4*)x;
    int f4base = b * 1024 * 16;
#pragma unroll
    for (int q = 0; q < 16; q++) {
        int idx = f4base + q * 1024 + t;
        if (idx < n * 16) {
            float nv = snorm[(idx >> 4) - b * 1024];
            float4 v = x4[idx];
            v.x *= nv; v.y *= nv; v.z *= nv; v.w *= nv;
            ((float4*)g_a)[idx] = v;
        }
    }
}

__global__ void k_csr(const int* __restrict__ src, const int* __restrict__ dst, int e) {
    int i = blockIdx.x * blockDim.x + threadIdx.x;
    if (i < e) {
        int p = atomicAdd(&g_fill[dst[i]], 1);
        g_col[p] = src[i];
    }
}

// ---------------- packed f32x2 helpers ----------------
__device__ __forceinline__ unsigned long long pk2(float x, float y) {
    unsigned long long r;
    asm("mov.b64 %0, {%1,%2};" : "=l"(r) : "f"(x), "f"(y));
    return r;
}
__device__ __forceinline__ void fma2(unsigned long long& d, unsigned long long a, unsigned long long b) {
    asm("fma.rn.f32x2 %0, %1, %2, %0;" : "+l"(d) : "l"(a), "l"(b));
}
__device__ __forceinline__ float2 upk2(unsigned long long v) {
    float2 r;
    asm("mov.b64 {%0,%1}, %2;" : "=f"(r.x), "=f"(r.y) : "l"(v));
    return r;
}

// ---------------- fused aggregation + tiled GEMM + epilogue ----------------
// Block = 256 threads, 64 nodes.
//  phase 1: warp w gathers nodes base+8w..base+8w+7 into sS[64][66].
//           int4 col loads (1 uniform LDG.128 per 4 edges) + 8-edge unroll
//           (8 independent float2 feature loads in flight). Dropout threefry
//           interleaved per node (ALU overlaps in-flight gathers).
//  phase 2: tiled GEMM on smem S (4 rows x 2 cpairs per thread) vs staged W
//  phase 3: epilogue (norm_dst, bias, relu, dropout, norm_src prescale)
template <int LAYER>
__global__ void __launch_bounds__(256) k_aggemm(const float* __restrict__ U,
                                                float* __restrict__ Unext,
                                                const float* __restrict__ W,
                                                const float* __restrict__ bias,
                                                uint32_t key0, uint32_t key1, int n) {
    __shared__ unsigned long long sW[64 * 32]; // [k][cpair] packed (W[k][2c], W[k][2c+1])
    __shared__ float sS[AGG_NPB * SS_STRIDE];  // [local node][k], padded
    int t = threadIdx.x;
    int base = blockIdx.x * AGG_NPB;
    int w = t >> 5, lane = t & 31;
    int rid = t >> 4;       // epilogue row id
    int cid = t & 15;       // epilogue col-pair id

    // stage W (16KB; one-time per 64 nodes)
    const float2* Wv = (const float2*)W;
#pragma unroll
    for (int q = 0; q < 8; q++) {
        int idx = t + q * 256;
        float2 wv = Wv[idx];
        sW[idx] = pk2(wv.x, wv.y);
    }

    // phase 1: gather-sum 8 nodes per warp (lane = col pair); dropout interleaved
    uint32_t keepmask = 0;
    const float2* T2 = (const float2*)U;
#pragma unroll 1
    for (int r = 0; r < 8; r++) {
        int node = base + w * 8 + r;
        float ax = 0.f, ay = 0.f;
        int s = 0, e = 0;
        if (node < n) { s = g_row_ptr[node]; e = g_row_ptr[node + 1]; }

        // dropout threefry for epilogue element pair r (overlaps gathers below)
        if (LAYER != 2) {
            int en = base + rid + 16 * (r >> 1);
            int ec = cid + 16 * (r & 1);
            uint32_t idx = (uint32_t)en * 64u + 2u * (uint32_t)ec;
            uint32_t y0, y1, z0, z1;
            d_threefry(key0, key1, 0u, idx, y0, y1);
            d_threefry(key0, key1, 0u, idx + 1u, z0, z1);
            keepmask |= (1u ^ ((y0 ^ y1) >> 31)) << (2 * r);
            keepmask |= (1u ^ ((z0 ^ z1) >> 31)) << (2 * r + 1);
        }

        int i = s;
        // head: align to int4 boundary
        for (; i < e && (i & 3); i++) {
            int u = g_col[i];
            float2 v = T2[u * 32 + lane];
            ax += v.x; ay += v.y;
        }
        // main: 8 edges / iter, 2 uniform LDG.128 col loads, 8 feature loads in flight
        for (; i + 8 <= e; i += 8) {
            int4 c0 = *(const int4*)&g_col[i];
            int4 c1 = *(const int4*)&g_col[i + 4];
            float2 v0 = T2[c0.x * 32 + lane];
            float2 v1 = T2[c0.y * 32 + lane];
            float2 v2 = T2[c0.z * 32 + lane];
            float2 v3 = T2[c0.w * 32 + lane];
            float2 v4 = T2[c1.x * 32 + lane];
            float2 v5 = T2[c1.y * 32 + lane];
            float2 v6 = T2[c1.z * 32 + lane];
            float2 v7 = T2[c1.w * 32 + lane];
            ax += ((v0.x + v1.x) + (v2.x + v3.x)) + ((v4.x + v5.x) + (v6.x + v7.x));
            ay += ((v0.y + v1.y) + (v2.y + v3.y)) + ((v4.y + v5.y) + (v6.y + v7.y));
        }
        // mid: 4 edges
        if (i + 4 <= e) {
            int4 c0 = *(const int4*)&g_col[i];
            float2 v0 = T2[c0.x * 32 + lane];
            float2 v1 = T2[c0.y * 32 + lane];
            float2 v2 = T2[c0.z * 32 + lane];
            float2 v3 = T2[c0.w * 32 + lane];
            ax += (v0.x + v1.x) + (v2.x + v3.x);
            ay += (v0.y + v1.y) + (v2.y + v3.y);
            i += 4;
        }
        // tail
        for (; i < e; i++) {
            int u = g_col[i];
            float2 v = T2[u * 32 + lane];
            ax += v.x; ay += v.y;
        }
        float* row = &sS[(w * 8 + r) * SS_STRIDE];
        ((float2*)row)[lane] = make_float2(ax, ay);  // cols 2*lane, 2*lane+1
    }
    __syncthreads();

    // phase 2: tiled GEMM. thread: rows rid+16i (i=0..3), cpairs cid+16j (j=0..1).
    unsigned long long acc[4][2];
#pragma unroll
    for (int i = 0; i < 4; i++)
#pragma unroll
        for (int j = 0; j < 2; j++) acc[i][j] = 0ull;

#pragma unroll 8
    for (int k = 0; k < 64; k++) {
        unsigned long long a[4], b[2];
#pragma unroll
        for (int i = 0; i < 4; i++) {
            float h = sS[(rid + 16 * i) * SS_STRIDE + k];
            a[i] = pk2(h, h);
        }
#pragma unroll
        for (int j = 0; j < 2; j++) b[j] = sW[k * 32 + cid + 16 * j];
#pragma unroll
        for (int i = 0; i < 4; i++)
#pragma unroll
            for (int j = 0; j < 2; j++) fma2(acc[i][j], a[i], b[j]);
    }

    // phase 3: epilogue (element pair r = 2*i + j  ->  keepmask bits 2r, 2r+1)
#pragma unroll
    for (int i = 0; i < 4; i++) {
        int node = base + rid + 16 * i;
        if (node < n) {
            float nd = g_norm_dst[node];
            float ns = (LAYER != 2) ? g_norm_src[node] : 0.f;
#pragma unroll
            for (int j = 0; j < 2; j++) {
                int c = cid + 16 * j;
                float2 bb = ((const float2*)bias)[c];
                float2 v = upk2(acc[i][j]);
                float ox = v.x * nd + bb.x;
                float oy = v.y * nd + bb.y;
                if (LAYER != 2) {
                    ox = fmaxf(ox, 0.f);
                    oy = fmaxf(oy, 0.f);
                    int r = 2 * i + j;
                    bool keep0 = (keepmask >> (2 * r)) & 1u;
                    bool keep1 = (keepmask >> (2 * r + 1)) & 1u;
                    ox = keep0 ? ox * 2.f * ns : 0.f;
                    oy = keep1 ? oy * 2.f * ns : 0.f;
                }
                ((float2*)Unext)[node * 32 + c] = make_float2(ox, oy);
            }
        }
    }
}

// ---------------- launch ----------------
extern "C" void kernel_launch(void* const* d_in, const int* in_sizes, int n_in,
                              void* d_out, int out_size) {
    const float* x  = (const float*)d_in[0];
    const float* W0 = (const float*)d_in[1];
    const float* b0 = (const float*)d_in[2];
    const float* W1 = (const float*)d_in[3];
    const float* b1 = (const float*)d_in[4];
    const float* W2 = (const float*)d_in[5];
    const float* b2 = (const float*)d_in[6];
    const int*   src = (const int*)d_in[7];
    const int*   dst = (const int*)d_in[8];
    int n = in_sizes[0] / 64;
    int e = in_sizes[7];
    float* out = (float*)d_out;

    int nb = (n + 1023) / 1024;  // <= 98: all scan blocks resident, lookback safe

    uint32_t d0k0, d0k1, d1k0, d1k1;
    h_threefry(0u, 1u, 0u, 0u, d0k0, d0k1);
    h_threefry(0u, 1u, 0u, 1u, d1k0, d1k1);

    float* gA; cudaGetSymbolAddress((void**)&gA, g_a);
    float* gB; cudaGetSymbolAddress((void**)&gB, g_b);
    void* pDegOut; cudaGetSymbolAddress(&pDegOut, g_deg_out);
    void* pDegIn;  cudaGetSymbolAddress(&pDegIn, g_deg_in);
    void* pFlag;   cudaGetSymbolAddress(&pFlag, g_blk_flag);

    int aB = (n + AGG_NPB - 1) / AGG_NPB;

    // zeroing via memset (not a kernel launch -> k_aggemm<0> lands in ncu slot 3)
    cudaMemsetAsync(pDegOut, 0, n * sizeof(int));
    cudaMemsetAsync(pDegIn, 0, n * sizeof(int));
    cudaMemsetAsync(pFlag, 0, NBLK_SCAN * sizeof(int));

    k_degree<<<(e + 255) / 256, 256>>>(src, dst, e);            // 0
    k_scan_norm_scale<<<nb, 1024>>>(x, n, e);                   // 1
    k_csr<<<(e + 255) / 256, 256>>>(src, dst, e);               // 2
    k_aggemm<0><<<aB, 256>>>(gA, gB, W0, b0, d0k0, d0k1, n);    // 3  (profiled)
    k_aggemm<1><<<aB, 256>>>(gB, gA, W1, b1, d1k0, d1k1, n);    // 4
    k_aggemm<2><<<aB, 256>>>(gA, out, W2, b2, 0u, 0u, n);       // 5
}